// round 6
// baseline (speedup 1.0000x reference)
#include <cuda_runtime.h>
#include <math.h>

// Problem constants
#define S        2048
#define ROWS     65536            // 2*16*2048 rows of x; also 32*2048 gemm outputs
#define TNB      64               // t-tile per partial-GEMM block
#define KCB      64               // k-chunk per partial-GEMM block
#define KSPLIT   32               // 2048 / KCB
#define NTILES   (S / TNB)        // 32 t-tiles

// Scratch (allocation-free rule: __device__ globals; zero-initialized)
__device__ int          g_idx[ROWS];
__device__ float        g_gather[ROWS];
__device__ float        g_part[KSPLIT * ROWS];   // 8 MB fp32 partials [ks][m][t]
__device__ unsigned int g_cnt[NTILES];           // finisher counters (self-resetting)

// ---------------------------------------------------------------------------
// Kernel A: one block per row. Copy x->out (float4) while reducing
// first-occurrence argmax of the row. Measured 6.79 TB/s (85% spec) — at the
// practical HBM ceiling; unchanged.
// ---------------------------------------------------------------------------
__global__ void __launch_bounds__(256)
copy_argmax_kernel(const float* __restrict__ x, float* __restrict__ out)
{
    const int row = blockIdx.x;
    const float4* __restrict__ xr = (const float4*)(x + (size_t)row * S);
    float4* __restrict__ orow     = (float4*)(out + (size_t)row * S);

    const int t = threadIdx.x;

    float best = -INFINITY;
    int   bidx = 0;

    #pragma unroll
    for (int i = 0; i < 2; i++) {
        const int e = t + i * 256;          // float4 index in row (0..511)
        float4 v = xr[e];
        orow[e] = v;
        const int base = e * 4;
        if (v.x > best) { best = v.x; bidx = base + 0; }
        if (v.y > best) { best = v.y; bidx = base + 1; }
        if (v.z > best) { best = v.z; bidx = base + 2; }
        if (v.w > best) { best = v.w; bidx = base + 3; }
    }

    #pragma unroll
    for (int off = 16; off > 0; off >>= 1) {
        float ov = __shfl_down_sync(0xFFFFFFFFu, best, off);
        int   oi = __shfl_down_sync(0xFFFFFFFFu, bidx, off);
        if (ov > best || (ov == best && oi < bidx)) { best = ov; bidx = oi; }
    }

    __shared__ float sv[8];
    __shared__ int   si[8];
    const int lane = t & 31;
    const int warp = t >> 5;
    if (lane == 0) { sv[warp] = best; si[warp] = bidx; }
    __syncthreads();

    if (warp == 0) {
        best = (lane < 8) ? sv[lane] : -INFINITY;
        bidx = (lane < 8) ? si[lane] : 0x7FFFFFFF;
        #pragma unroll
        for (int off = 4; off > 0; off >>= 1) {
            float ov = __shfl_down_sync(0xFFFFFFFFu, best, off);
            int   oi = __shfl_down_sync(0xFFFFFFFFu, bidx, off);
            if (ov > best || (ov == best && oi < bidx)) { best = ov; bidx = oi; }
        }
        if (lane == 0) {
            g_idx[row]    = bidx;
            g_gather[row] = best;
        }
    }
}

// ---------------------------------------------------------------------------
// Kernel B: k-split partial GEMM with fused finisher reduction.
// Grid (32 t-tiles, 32 ksplit) = 1024 blocks, 128 threads.
// Each block: partial C[32][64] over one 64-wide k-chunk (R4 layout: scalar
// LDS inner loop, 4m x 4t register tile). After storing its partial it bumps
// the per-tile counter; the LAST block for a tile sums all 32 partials in
// fixed ks order (deterministic), adds bias, exact-erf GELU, scatters.
// ---------------------------------------------------------------------------
__global__ void __launch_bounds__(128)
gemm_fused_kernel(const float* __restrict__ W,
                  const float* __restrict__ bias,
                  float* __restrict__ out)
{
    __shared__ float gs[32][KCB + 1];    // [m][k]
    __shared__ float ws[TNB][KCB + 1];   // [t][k]

    const int t0  = blockIdx.x * TNB;
    const int k0  = blockIdx.y * KCB;
    const int tid = threadIdx.x;

    // Fill gs: 32 rows x 64 cols. thread -> row tid>>2, 16-col segment (tid&3)*16
    {
        const int m  = tid >> 2;
        const int cb = (tid & 3) * 16;
        #pragma unroll
        for (int j = 0; j < 4; j++) {
            float4 v = *(const float4*)(g_gather + (size_t)m * S + k0 + cb + j * 4);
            gs[m][cb + j*4 + 0] = v.x; gs[m][cb + j*4 + 1] = v.y;
            gs[m][cb + j*4 + 2] = v.z; gs[m][cb + j*4 + 3] = v.w;
        }
    }
    // Fill ws: 64 rows x 64 cols. thread -> row tid>>1, 32-col segment (tid&1)*32
    {
        const int t  = tid >> 1;
        const int cb = (tid & 1) * 32;
        #pragma unroll
        for (int j = 0; j < 8; j++) {
            float4 v = *(const float4*)(W + (size_t)(t0 + t) * S + k0 + cb + j * 4);
            ws[t][cb + j*4 + 0] = v.x; ws[t][cb + j*4 + 1] = v.y;
            ws[t][cb + j*4 + 2] = v.z; ws[t][cb + j*4 + 3] = v.w;
        }
    }
    __syncthreads();

    const int m0  = (tid & 7) * 4;    // 8 m-groups
    const int tn0 = (tid >> 3) * 4;   // 16 t-groups

    float acc[4][4] = {};

    #pragma unroll 8
    for (int k = 0; k < KCB; k++) {
        const float a0 = gs[m0 + 0][k];
        const float a1 = gs[m0 + 1][k];
        const float a2 = gs[m0 + 2][k];
        const float a3 = gs[m0 + 3][k];
        const float w0 = ws[tn0 + 0][k];
        const float w1 = ws[tn0 + 1][k];
        const float w2 = ws[tn0 + 2][k];
        const float w3 = ws[tn0 + 3][k];
        acc[0][0] = fmaf(a0, w0, acc[0][0]); acc[0][1] = fmaf(a0, w1, acc[0][1]);
        acc[0][2] = fmaf(a0, w2, acc[0][2]); acc[0][3] = fmaf(a0, w3, acc[0][3]);
        acc[1][0] = fmaf(a1, w0, acc[1][0]); acc[1][1] = fmaf(a1, w1, acc[1][1]);
        acc[1][2] = fmaf(a1, w2, acc[1][2]); acc[1][3] = fmaf(a1, w3, acc[1][3]);
        acc[2][0] = fmaf(a2, w0, acc[2][0]); acc[2][1] = fmaf(a2, w1, acc[2][1]);
        acc[2][2] = fmaf(a2, w2, acc[2][2]); acc[2][3] = fmaf(a2, w3, acc[2][3]);
        acc[3][0] = fmaf(a3, w0, acc[3][0]); acc[3][1] = fmaf(a3, w1, acc[3][1]);
        acc[3][2] = fmaf(a3, w2, acc[3][2]); acc[3][3] = fmaf(a3, w3, acc[3][3]);
    }

    // Store partial tile
    float* p = g_part + (size_t)blockIdx.y * ROWS;
    #pragma unroll
    for (int i = 0; i < 4; i++) {
        #pragma unroll
        for (int j = 0; j < 4; j++) {
            p[(size_t)(m0 + i) * S + t0 + tn0 + j] = acc[i][j];
        }
    }

    // ---- Finisher handoff (threadFenceReduction pattern) ----
    __threadfence();            // make this thread's partial stores visible
    __syncthreads();            // all threads of block have fenced

    __shared__ unsigned int s_last;
    if (tid == 0) {
        unsigned int old = atomicAdd(&g_cnt[blockIdx.x], 1u);
        s_last = (old == KSPLIT - 1) ? 1u : 0u;
    }
    __syncthreads();

    if (s_last) {
        // This block reduces the whole t-tile: 32 m x 64 t = 2048 outputs,
        // 16 per thread. Fixed ks summation order -> deterministic.
        const int mf = tid >> 2;          // 0..31
        const int tg = (tid & 3) * 16;    // 16 consecutive t, as 4 float4

        float4 accr[4] = {};
        for (int ks = 0; ks < KSPLIT; ks++) {
            const float* pp = g_part + (size_t)ks * ROWS + (size_t)mf * S + t0 + tg;
            #pragma unroll
            for (int j = 0; j < 4; j++) {
                float4 v = *(const float4*)(pp + j * 4);
                accr[j].x += v.x; accr[j].y += v.y;
                accr[j].z += v.z; accr[j].w += v.w;
            }
        }

        #pragma unroll
        for (int j = 0; j < 4; j++) {
            float vals[4] = { accr[j].x, accr[j].y, accr[j].z, accr[j].w };
            #pragma unroll
            for (int c = 0; c < 4; c++) {
                const int t = t0 + tg + j * 4 + c;
                const float v  = vals[c] + bias[t];
                const float ge = 0.5f * v * (1.0f + erff(v * 0.70710678118654752f));
                const size_t r = (size_t)mf * S + t;
                out[r * (size_t)S + (size_t)g_idx[r]] = ge;
            }
        }

        __syncthreads();
        if (tid == 0) g_cnt[blockIdx.x] = 0;   // reset for next graph replay
    }
}

// ---------------------------------------------------------------------------
extern "C" void kernel_launch(void* const* d_in, const int* in_sizes, int n_in,
                              void* d_out, int out_size)
{
    const float* x    = (const float*)d_in[0];   // [2,16,2048,2048]
    const float* W    = (const float*)d_in[1];   // [2048,2048]
    const float* bias = (const float*)d_in[2];   // [2048]
    float* out        = (float*)d_out;

    copy_argmax_kernel<<<ROWS, 256>>>(x, out);
    gemm_fused_kernel<<<dim3(NTILES, KSPLIT), 128>>>(W, bias, out);
}

// round 8
// speedup vs baseline: 1.0569x; 1.0569x over previous
#include <cuda_runtime.h>
#include <math.h>

// Problem constants
#define S        2048
#define ROWS     65536            // 2*16*2048 rows of x; also 32*2048 gemm outputs
#define TNB      64               // t-tile per partial-GEMM block
#define KCB      32               // k-chunk per partial-GEMM block
#define KSPLIT   64               // 2048 / KCB
#define NTILES   (S / TNB)        // 32 t-tiles

// Scratch (allocation-free rule: __device__ globals)
__device__ int   g_idx[ROWS];
__device__ float g_gather[ROWS];
__device__ float g_part[KSPLIT * ROWS];   // 16 MB fp32 partials [ks][m][t]

// ---------------------------------------------------------------------------
// Kernel A: one block per row. Copy x->out (float4) while reducing
// first-occurrence argmax of the row. Measured 6.79 TB/s (85% spec) — at the
// practical HBM ceiling; unchanged from R3.
// ---------------------------------------------------------------------------
__global__ void __launch_bounds__(256)
copy_argmax_kernel(const float* __restrict__ x, float* __restrict__ out)
{
    const int row = blockIdx.x;
    const float4* __restrict__ xr = (const float4*)(x + (size_t)row * S);
    float4* __restrict__ orow     = (float4*)(out + (size_t)row * S);

    const int t = threadIdx.x;

    float best = -INFINITY;
    int   bidx = 0;

    #pragma unroll
    for (int i = 0; i < 2; i++) {
        const int e = t + i * 256;          // float4 index in row (0..511)
        float4 v = xr[e];
        orow[e] = v;
        const int base = e * 4;
        if (v.x > best) { best = v.x; bidx = base + 0; }
        if (v.y > best) { best = v.y; bidx = base + 1; }
        if (v.z > best) { best = v.z; bidx = base + 2; }
        if (v.w > best) { best = v.w; bidx = base + 3; }
    }

    #pragma unroll
    for (int off = 16; off > 0; off >>= 1) {
        float ov = __shfl_down_sync(0xFFFFFFFFu, best, off);
        int   oi = __shfl_down_sync(0xFFFFFFFFu, bidx, off);
        if (ov > best || (ov == best && oi < bidx)) { best = ov; bidx = oi; }
    }

    __shared__ float sv[8];
    __shared__ int   si[8];
    const int lane = t & 31;
    const int warp = t >> 5;
    if (lane == 0) { sv[warp] = best; si[warp] = bidx; }
    __syncthreads();

    if (warp == 0) {
        best = (lane < 8) ? sv[lane] : -INFINITY;
        bidx = (lane < 8) ? si[lane] : 0x7FFFFFFF;
        #pragma unroll
        for (int off = 4; off > 0; off >>= 1) {
            float ov = __shfl_down_sync(0xFFFFFFFFu, best, off);
            int   oi = __shfl_down_sync(0xFFFFFFFFu, bidx, off);
            if (ov > best || (ov == best && oi < bidx)) { best = ov; bidx = oi; }
        }
        if (lane == 0) {
            g_idx[row]    = bidx;
            g_gather[row] = best;
        }
    }
}

// ---------------------------------------------------------------------------
// Kernel B1: k-split partial GEMM. Grid (32 t-tiles, 64 ksplit) = 2048 blocks,
// 128 threads. Block computes partial C[32][64] over one 32-wide k-chunk.
// Register tile 4m x 4t per thread (16 FMA : 8 LDS per k). smem 12.6 KB.
// ---------------------------------------------------------------------------
__global__ void __launch_bounds__(128)
gemm_partial_kernel(const float* __restrict__ W)
{
    __shared__ float gs[32][KCB + 1];    // [m][k]
    __shared__ float ws[TNB][KCB + 1];   // [t][k]

    const int t0  = blockIdx.x * TNB;
    const int k0  = blockIdx.y * KCB;
    const int tid = threadIdx.x;

    // Fill gs: 32 rows x 32 cols. thread -> row tid>>2, 8-col segment (tid&3)*8
    {
        const int m  = tid >> 2;
        const int cb = (tid & 3) * 8;
        #pragma unroll
        for (int j = 0; j < 2; j++) {
            float4 v = *(const float4*)(g_gather + (size_t)m * S + k0 + cb + j * 4);
            gs[m][cb + j*4 + 0] = v.x; gs[m][cb + j*4 + 1] = v.y;
            gs[m][cb + j*4 + 2] = v.z; gs[m][cb + j*4 + 3] = v.w;
        }
    }
    // Fill ws: 64 rows x 32 cols. thread -> row tid>>1, 16-col segment (tid&1)*16
    {
        const int t  = tid >> 1;
        const int cb = (tid & 1) * 16;
        #pragma unroll
        for (int j = 0; j < 4; j++) {
            float4 v = *(const float4*)(W + (size_t)(t0 + t) * S + k0 + cb + j * 4);
            ws[t][cb + j*4 + 0] = v.x; ws[t][cb + j*4 + 1] = v.y;
            ws[t][cb + j*4 + 2] = v.z; ws[t][cb + j*4 + 3] = v.w;
        }
    }
    __syncthreads();

    const int m0  = (tid & 7) * 4;    // 8 m-groups
    const int tn0 = (tid >> 3) * 4;   // 16 t-groups

    float acc[4][4] = {};

    #pragma unroll 8
    for (int k = 0; k < KCB; k++) {
        const float a0 = gs[m0 + 0][k];
        const float a1 = gs[m0 + 1][k];
        const float a2 = gs[m0 + 2][k];
        const float a3 = gs[m0 + 3][k];
        const float w0 = ws[tn0 + 0][k];
        const float w1 = ws[tn0 + 1][k];
        const float w2 = ws[tn0 + 2][k];
        const float w3 = ws[tn0 + 3][k];
        acc[0][0] = fmaf(a0, w0, acc[0][0]); acc[0][1] = fmaf(a0, w1, acc[0][1]);
        acc[0][2] = fmaf(a0, w2, acc[0][2]); acc[0][3] = fmaf(a0, w3, acc[0][3]);
        acc[1][0] = fmaf(a1, w0, acc[1][0]); acc[1][1] = fmaf(a1, w1, acc[1][1]);
        acc[1][2] = fmaf(a1, w2, acc[1][2]); acc[1][3] = fmaf(a1, w3, acc[1][3]);
        acc[2][0] = fmaf(a2, w0, acc[2][0]); acc[2][1] = fmaf(a2, w1, acc[2][1]);
        acc[2][2] = fmaf(a2, w2, acc[2][2]); acc[2][3] = fmaf(a2, w3, acc[2][3]);
        acc[3][0] = fmaf(a3, w0, acc[3][0]); acc[3][1] = fmaf(a3, w1, acc[3][1]);
        acc[3][2] = fmaf(a3, w2, acc[3][2]); acc[3][3] = fmaf(a3, w3, acc[3][3]);
    }

    float* p = g_part + (size_t)blockIdx.y * ROWS;
    #pragma unroll
    for (int i = 0; i < 4; i++) {
        float4 v = make_float4(acc[i][0], acc[i][1], acc[i][2], acc[i][3]);
        *(float4*)(p + (size_t)(m0 + i) * S + t0 + tn0) = v;
    }
}

// ---------------------------------------------------------------------------
// Kernel B2: reduce KSPLIT partials (fixed order -> deterministic), + bias,
// exact-erf GELU, scatter into out at argmax positions.
// float4 per thread: 16384 threads, 64 LDG.128 each (high MLP).
// ---------------------------------------------------------------------------
__global__ void __launch_bounds__(256)
reduce_gelu_scatter_kernel(const float* __restrict__ bias,
                           float* __restrict__ out)
{
    const int r4 = (blockIdx.x * 256 + threadIdx.x) * 4;   // base of 4 outputs

    float4 s = make_float4(0.f, 0.f, 0.f, 0.f);
    #pragma unroll
    for (int ks = 0; ks < KSPLIT; ks++) {
        float4 v = *(const float4*)(g_part + (size_t)ks * ROWS + r4);
        s.x += v.x; s.y += v.y; s.z += v.z; s.w += v.w;
    }

    const float vals[4] = { s.x, s.y, s.z, s.w };
    #pragma unroll
    for (int c = 0; c < 4; c++) {
        const int r = r4 + c;
        const int t = r & (S - 1);
        const float v  = vals[c] + bias[t];
        const float ge = 0.5f * v * (1.0f + erff(v * 0.70710678118654752f));
        out[(size_t)r * S + (size_t)g_idx[r]] = ge;
    }
}

// ---------------------------------------------------------------------------
extern "C" void kernel_launch(void* const* d_in, const int* in_sizes, int n_in,
                              void* d_out, int out_size)
{
    const float* x    = (const float*)d_in[0];   // [2,16,2048,2048]
    const float* W    = (const float*)d_in[1];   // [2048,2048]
    const float* bias = (const float*)d_in[2];   // [2048]
    float* out        = (float*)d_out;

    copy_argmax_kernel<<<ROWS, 256>>>(x, out);
    gemm_partial_kernel<<<dim3(NTILES, KSPLIT), 128>>>(W);
    reduce_gelu_scatter_kernel<<<ROWS / (256 * 4), 256>>>(bias, out);
}

// round 9
// speedup vs baseline: 1.0667x; 1.0092x over previous
#include <cuda_runtime.h>
#include <math.h>

// Problem constants
#define S        2048
#define ROWS     65536            // 2*16*2048 rows of x; also 32*2048 gemm outputs
#define TNB      64               // t-tile per partial-GEMM block
#define KCB      64               // k-chunk per partial-GEMM block
#define KSPLIT   32               // 2048 / KCB
#define NTILES   (S / TNB)        // 32 t-tiles

// Scratch (allocation-free rule: __device__ globals)
__device__ int   g_idx[ROWS];
__device__ float g_gather[ROWS];
__device__ float g_part[KSPLIT * ROWS];   // 8 MB fp32 partials [ks][m][t]

// ---------------------------------------------------------------------------
// Kernel A: one block per row. Copy x->out (float4) while reducing
// first-occurrence argmax of the row. 6.8-6.9 TB/s across 4 rounds — at the
// practical HBM ceiling; unchanged.
// ---------------------------------------------------------------------------
__global__ void __launch_bounds__(256)
copy_argmax_kernel(const float* __restrict__ x, float* __restrict__ out)
{
    const int row = blockIdx.x;
    const float4* __restrict__ xr = (const float4*)(x + (size_t)row * S);
    float4* __restrict__ orow     = (float4*)(out + (size_t)row * S);

    const int t = threadIdx.x;

    float best = -INFINITY;
    int   bidx = 0;

    #pragma unroll
    for (int i = 0; i < 2; i++) {
        const int e = t + i * 256;          // float4 index in row (0..511)
        float4 v = xr[e];
        orow[e] = v;
        const int base = e * 4;
        if (v.x > best) { best = v.x; bidx = base + 0; }
        if (v.y > best) { best = v.y; bidx = base + 1; }
        if (v.z > best) { best = v.z; bidx = base + 2; }
        if (v.w > best) { best = v.w; bidx = base + 3; }
    }

    #pragma unroll
    for (int off = 16; off > 0; off >>= 1) {
        float ov = __shfl_down_sync(0xFFFFFFFFu, best, off);
        int   oi = __shfl_down_sync(0xFFFFFFFFu, bidx, off);
        if (ov > best || (ov == best && oi < bidx)) { best = ov; bidx = oi; }
    }

    __shared__ float sv[8];
    __shared__ int   si[8];
    const int lane = t & 31;
    const int warp = t >> 5;
    if (lane == 0) { sv[warp] = best; si[warp] = bidx; }
    __syncthreads();

    if (warp == 0) {
        best = (lane < 8) ? sv[lane] : -INFINITY;
        bidx = (lane < 8) ? si[lane] : 0x7FFFFFFF;
        #pragma unroll
        for (int off = 4; off > 0; off >>= 1) {
            float ov = __shfl_down_sync(0xFFFFFFFFu, best, off);
            int   oi = __shfl_down_sync(0xFFFFFFFFu, bidx, off);
            if (ov > best || (ov == best && oi < bidx)) { best = ov; bidx = oi; }
        }
        if (lane == 0) {
            g_idx[row]    = bidx;
            g_gather[row] = best;
        }
    }
}

// ---------------------------------------------------------------------------
// Kernel B1: k-split partial GEMM (R3 geometry). Grid (32, 32) = 1024 blocks,
// 128 threads. PDL: fills the W smem tile (independent of kernel A) before
// cudaGridDependencySynchronize(), then reads g_gather. 4m x 4t register tile.
// ---------------------------------------------------------------------------
__global__ void __launch_bounds__(128)
gemm_partial_kernel(const float* __restrict__ W)
{
    __shared__ float gs[32][KCB + 1];    // [m][k]
    __shared__ float ws[TNB][KCB + 1];   // [t][k]

    const int t0  = blockIdx.x * TNB;
    const int k0  = blockIdx.y * KCB;
    const int tid = threadIdx.x;

    // --- A-independent preamble: fill ws from W (overlaps kernel A tail) ---
    // 64 rows x 64 cols. thread -> row tid>>1, 32-col segment (tid&1)*32
    {
        const int t  = tid >> 1;
        const int cb = (tid & 1) * 32;
        #pragma unroll
        for (int j = 0; j < 8; j++) {
            float4 v = *(const float4*)(W + (size_t)(t0 + t) * S + k0 + cb + j * 4);
            ws[t][cb + j*4 + 0] = v.x; ws[t][cb + j*4 + 1] = v.y;
            ws[t][cb + j*4 + 2] = v.z; ws[t][cb + j*4 + 3] = v.w;
        }
    }

    // --- Wait for kernel A's writes (g_gather) to be visible ---
    cudaGridDependencySynchronize();

    // Fill gs: 32 rows x 64 cols. thread -> row tid>>2, 16-col segment (tid&3)*16
    {
        const int m  = tid >> 2;
        const int cb = (tid & 3) * 16;
        #pragma unroll
        for (int j = 0; j < 4; j++) {
            float4 v = *(const float4*)(g_gather + (size_t)m * S + k0 + cb + j * 4);
            gs[m][cb + j*4 + 0] = v.x; gs[m][cb + j*4 + 1] = v.y;
            gs[m][cb + j*4 + 2] = v.z; gs[m][cb + j*4 + 3] = v.w;
        }
    }
    __syncthreads();

    const int m0  = (tid & 7) * 4;    // 8 m-groups
    const int tn0 = (tid >> 3) * 4;   // 16 t-groups

    float acc[4][4] = {};

    #pragma unroll 8
    for (int k = 0; k < KCB; k++) {
        const float a0 = gs[m0 + 0][k];
        const float a1 = gs[m0 + 1][k];
        const float a2 = gs[m0 + 2][k];
        const float a3 = gs[m0 + 3][k];
        const float w0 = ws[tn0 + 0][k];
        const float w1 = ws[tn0 + 1][k];
        const float w2 = ws[tn0 + 2][k];
        const float w3 = ws[tn0 + 3][k];
        acc[0][0] = fmaf(a0, w0, acc[0][0]); acc[0][1] = fmaf(a0, w1, acc[0][1]);
        acc[0][2] = fmaf(a0, w2, acc[0][2]); acc[0][3] = fmaf(a0, w3, acc[0][3]);
        acc[1][0] = fmaf(a1, w0, acc[1][0]); acc[1][1] = fmaf(a1, w1, acc[1][1]);
        acc[1][2] = fmaf(a1, w2, acc[1][2]); acc[1][3] = fmaf(a1, w3, acc[1][3]);
        acc[2][0] = fmaf(a2, w0, acc[2][0]); acc[2][1] = fmaf(a2, w1, acc[2][1]);
        acc[2][2] = fmaf(a2, w2, acc[2][2]); acc[2][3] = fmaf(a2, w3, acc[2][3]);
        acc[3][0] = fmaf(a3, w0, acc[3][0]); acc[3][1] = fmaf(a3, w1, acc[3][1]);
        acc[3][2] = fmaf(a3, w2, acc[3][2]); acc[3][3] = fmaf(a3, w3, acc[3][3]);
    }

    float* p = g_part + (size_t)blockIdx.y * ROWS;
    #pragma unroll
    for (int i = 0; i < 4; i++) {
        float4 v = make_float4(acc[i][0], acc[i][1], acc[i][2], acc[i][3]);
        *(float4*)(p + (size_t)(m0 + i) * S + t0 + tn0) = v;
    }
}

// ---------------------------------------------------------------------------
// Kernel B2: reduce KSPLIT partials (fixed ks order -> deterministic), + bias,
// exact-erf GELU, scatter into out. 512 blocks x 128 threads, one output each;
// 32 unrolled coalesced loads per thread. PDL overlaps launch with B1 tail.
// ---------------------------------------------------------------------------
__global__ void __launch_bounds__(128)
reduce_gelu_scatter_kernel(const float* __restrict__ bias,
                           float* __restrict__ out)
{
    const int r = blockIdx.x * 128 + threadIdx.x;   // 0..65535  (= m*S + t)
    const int t = r & (S - 1);
    const float bv = bias[t];                        // independent of B1

    cudaGridDependencySynchronize();

    float s = 0.0f;
    #pragma unroll
    for (int ks = 0; ks < KSPLIT; ks++)
        s += g_part[(size_t)ks * ROWS + r];

    const float v  = s + bv;
    const float ge = 0.5f * v * (1.0f + erff(v * 0.70710678118654752f));
    out[(size_t)r * S + (size_t)g_idx[r]] = ge;
}

// ---------------------------------------------------------------------------
extern "C" void kernel_launch(void* const* d_in, const int* in_sizes, int n_in,
                              void* d_out, int out_size)
{
    const float* x    = (const float*)d_in[0];   // [2,16,2048,2048]
    const float* W    = (const float*)d_in[1];   // [2048,2048]
    const float* bias = (const float*)d_in[2];   // [2048]
    float* out        = (float*)d_out;

    copy_argmax_kernel<<<ROWS, 256>>>(x, out);

    // B1 with programmatic dependent launch (overlap W fill with A's tail)
    {
        cudaLaunchConfig_t cfg = {};
        cfg.gridDim  = dim3(NTILES, KSPLIT);
        cfg.blockDim = dim3(128);
        cfg.stream   = 0;
        cudaLaunchAttribute attr[1];
        attr[0].id = cudaLaunchAttributeProgrammaticStreamSerialization;
        attr[0].val.programmaticStreamSerializationAllowed = 1;
        cfg.attrs = attr;
        cfg.numAttrs = 1;
        cudaLaunchKernelEx(&cfg, gemm_partial_kernel, W);
    }

    // B2 with PDL (overlap launch/preamble with B1's tail)
    {
        cudaLaunchConfig_t cfg = {};
        cfg.gridDim  = dim3(ROWS / 128);
        cfg.blockDim = dim3(128);
        cfg.stream   = 0;
        cudaLaunchAttribute attr[1];
        attr[0].id = cudaLaunchAttributeProgrammaticStreamSerialization;
        attr[0].val.programmaticStreamSerializationAllowed = 1;
        cfg.attrs = attr;
        cfg.numAttrs = 1;
        cudaLaunchKernelEx(&cfg, reduce_gelu_scatter_kernel, bias, out);
    }
}

// round 10
// speedup vs baseline: 1.0733x; 1.0062x over previous
#include <cuda_runtime.h>
#include <math.h>

// Problem constants
#define S        2048
#define ROWS     65536            // 2*16*2048 rows of x; also 32*2048 gemm outputs
#define TNB      64               // t-tile per partial-GEMM block
#define KCB      64               // k-chunk per partial-GEMM block
#define KSPLIT   32               // 2048 / KCB
#define NTILES   (S / TNB)        // 32 t-tiles

// Scratch (allocation-free rule: __device__ globals)
__device__ int   g_idx[ROWS];
__device__ float g_gather[ROWS];
__device__ float g_part[KSPLIT * ROWS];   // 8 MB fp32 partials [ks][m][t]

// ---------------------------------------------------------------------------
// Kernel A: one block per row. Copy x->out (float4) while reducing
// first-occurrence argmax of the row. 6.8-6.9 TB/s over 5 rounds — at the
// practical HBM ceiling; frozen.
// ---------------------------------------------------------------------------
__global__ void __launch_bounds__(256)
copy_argmax_kernel(const float* __restrict__ x, float* __restrict__ out)
{
    const int row = blockIdx.x;
    const float4* __restrict__ xr = (const float4*)(x + (size_t)row * S);
    float4* __restrict__ orow     = (float4*)(out + (size_t)row * S);

    const int t = threadIdx.x;

    float best = -INFINITY;
    int   bidx = 0;

    #pragma unroll
    for (int i = 0; i < 2; i++) {
        const int e = t + i * 256;          // float4 index in row (0..511)
        float4 v = xr[e];
        orow[e] = v;
        const int base = e * 4;
        if (v.x > best) { best = v.x; bidx = base + 0; }
        if (v.y > best) { best = v.y; bidx = base + 1; }
        if (v.z > best) { best = v.z; bidx = base + 2; }
        if (v.w > best) { best = v.w; bidx = base + 3; }
    }

    #pragma unroll
    for (int off = 16; off > 0; off >>= 1) {
        float ov = __shfl_down_sync(0xFFFFFFFFu, best, off);
        int   oi = __shfl_down_sync(0xFFFFFFFFu, bidx, off);
        if (ov > best || (ov == best && oi < bidx)) { best = ov; bidx = oi; }
    }

    __shared__ float sv[8];
    __shared__ int   si[8];
    const int lane = t & 31;
    const int warp = t >> 5;
    if (lane == 0) { sv[warp] = best; si[warp] = bidx; }
    __syncthreads();

    if (warp == 0) {
        best = (lane < 8) ? sv[lane] : -INFINITY;
        bidx = (lane < 8) ? si[lane] : 0x7FFFFFFF;
        #pragma unroll
        for (int off = 4; off > 0; off >>= 1) {
            float ov = __shfl_down_sync(0xFFFFFFFFu, best, off);
            int   oi = __shfl_down_sync(0xFFFFFFFFu, bidx, off);
            if (ov > best || (ov == best && oi < bidx)) { best = ov; bidx = oi; }
        }
        if (lane == 0) {
            g_idx[row]    = bidx;
            g_gather[row] = best;
        }
    }
}

// ---------------------------------------------------------------------------
// tf32 helpers
// ---------------------------------------------------------------------------
__device__ __forceinline__ unsigned f2tf32(float f) {
    unsigned u;
    asm("cvt.rna.tf32.f32 %0, %1;" : "=r"(u) : "f"(f));
    return u;
}

__device__ __forceinline__ void mma_tf32_16x8x8(
    float& c0, float& c1, float& c2, float& c3,
    unsigned a0, unsigned a1, unsigned a2, unsigned a3,
    unsigned b0, unsigned b1)
{
    asm volatile(
        "mma.sync.aligned.m16n8k8.row.col.f32.tf32.tf32.f32 "
        "{%0,%1,%2,%3}, {%4,%5,%6,%7}, {%8,%9}, {%0,%1,%2,%3};"
        : "+f"(c0), "+f"(c1), "+f"(c2), "+f"(c3)
        : "r"(a0), "r"(a1), "r"(a2), "r"(a3), "r"(b0), "r"(b1));
}

// ---------------------------------------------------------------------------
// Kernel B1: k-split partial GEMM on tensor cores (tf32 mma.sync).
// Grid (32, 32) = 1024 blocks, 128 threads (4 warps).
// Warp w: m-half (w&1)*16, t-quarter (w>>1)*32. 32 HMMA per warp.
// PDL: W tile fill precedes cudaGridDependencySynchronize().
// ---------------------------------------------------------------------------
__global__ void __launch_bounds__(128)
gemm_partial_kernel(const float* __restrict__ W)
{
    __shared__ unsigned gs[32][KCB + 1];   // [m][k], tf32 bits
    __shared__ unsigned ws[TNB][KCB + 1];  // [t][k], tf32 bits

    const int t0  = blockIdx.x * TNB;
    const int k0  = blockIdx.y * KCB;
    const int tid = threadIdx.x;

    // --- A-independent preamble: fill ws from W (overlaps kernel A tail) ---
    {
        const int t  = tid >> 1;
        const int cb = (tid & 1) * 32;
        #pragma unroll
        for (int j = 0; j < 8; j++) {
            float4 v = *(const float4*)(W + (size_t)(t0 + t) * S + k0 + cb + j * 4);
            ws[t][cb + j*4 + 0] = f2tf32(v.x); ws[t][cb + j*4 + 1] = f2tf32(v.y);
            ws[t][cb + j*4 + 2] = f2tf32(v.z); ws[t][cb + j*4 + 3] = f2tf32(v.w);
        }
    }

    cudaGridDependencySynchronize();

    // Fill gs from g_gather
    {
        const int m  = tid >> 2;
        const int cb = (tid & 3) * 16;
        #pragma unroll
        for (int j = 0; j < 4; j++) {
            float4 v = *(const float4*)(g_gather + (size_t)m * S + k0 + cb + j * 4);
            gs[m][cb + j*4 + 0] = f2tf32(v.x); gs[m][cb + j*4 + 1] = f2tf32(v.y);
            gs[m][cb + j*4 + 2] = f2tf32(v.z); gs[m][cb + j*4 + 3] = f2tf32(v.w);
        }
    }
    __syncthreads();

    const int lane = tid & 31;
    const int w    = tid >> 5;
    const int mh   = (w & 1) * 16;     // m-half base
    const int tq   = (w >> 1) * 32;    // t-quarter base

    const int ar = lane >> 2;          // 0..7
    const int ac = lane & 3;           // 0..3

    float c[4][4] = {};

    #pragma unroll
    for (int ks = 0; ks < 8; ks++) {
        const int col = ks * 8 + ac;
        const unsigned a0 = gs[mh + ar    ][col];
        const unsigned a1 = gs[mh + ar + 8][col];
        const unsigned a2 = gs[mh + ar    ][col + 4];
        const unsigned a3 = gs[mh + ar + 8][col + 4];
        #pragma unroll
        for (int nt = 0; nt < 4; nt++) {
            const int n = tq + nt * 8 + ar;          // B[k][n] = ws[n][k]
            const unsigned b0 = ws[n][col];
            const unsigned b1 = ws[n][col + 4];
            mma_tf32_16x8x8(c[nt][0], c[nt][1], c[nt][2], c[nt][3],
                            a0, a1, a2, a3, b0, b1);
        }
    }

    // Store partials. C frag m16n8: (c0,c1) at row mh+ar, cols 2*ac, 2*ac+1;
    // (c2,c3) at row mh+ar+8.
    float* p = g_part + (size_t)blockIdx.y * ROWS;
    #pragma unroll
    for (int nt = 0; nt < 4; nt++) {
        const int tcol = t0 + tq + nt * 8 + 2 * ac;
        *(float2*)(p + (size_t)(mh + ar    ) * S + tcol) = make_float2(c[nt][0], c[nt][1]);
        *(float2*)(p + (size_t)(mh + ar + 8) * S + tcol) = make_float2(c[nt][2], c[nt][3]);
    }
}

// ---------------------------------------------------------------------------
// Kernel B2: reduce KSPLIT partials (fixed ks order -> deterministic), + bias,
// exact-erf GELU, scatter into out. 512 blocks x 128 threads. PDL.
// ---------------------------------------------------------------------------
__global__ void __launch_bounds__(128)
reduce_gelu_scatter_kernel(const float* __restrict__ bias,
                           float* __restrict__ out)
{
    const int r = blockIdx.x * 128 + threadIdx.x;   // 0..65535  (= m*S + t)
    const int t = r & (S - 1);
    const float bv = bias[t];                        // independent of B1

    cudaGridDependencySynchronize();

    float s = 0.0f;
    #pragma unroll
    for (int ks = 0; ks < KSPLIT; ks++)
        s += g_part[(size_t)ks * ROWS + r];

    const float v  = s + bv;
    const float ge = 0.5f * v * (1.0f + erff(v * 0.70710678118654752f));
    out[(size_t)r * S + (size_t)g_idx[r]] = ge;
}

// ---------------------------------------------------------------------------
extern "C" void kernel_launch(void* const* d_in, const int* in_sizes, int n_in,
                              void* d_out, int out_size)
{
    const float* x    = (const float*)d_in[0];   // [2,16,2048,2048]
    const float* W    = (const float*)d_in[1];   // [2048,2048]
    const float* bias = (const float*)d_in[2];   // [2048]
    float* out        = (float*)d_out;

    copy_argmax_kernel<<<ROWS, 256>>>(x, out);

    {
        cudaLaunchConfig_t cfg = {};
        cfg.gridDim  = dim3(NTILES, KSPLIT);
        cfg.blockDim = dim3(128);
        cfg.stream   = 0;
        cudaLaunchAttribute attr[1];
        attr[0].id = cudaLaunchAttributeProgrammaticStreamSerialization;
        attr[0].val.programmaticStreamSerializationAllowed = 1;
        cfg.attrs = attr;
        cfg.numAttrs = 1;
        cudaLaunchKernelEx(&cfg, gemm_partial_kernel, W);
    }

    {
        cudaLaunchConfig_t cfg = {};
        cfg.gridDim  = dim3(ROWS / 128);
        cfg.blockDim = dim3(128);
        cfg.stream   = 0;
        cudaLaunchAttribute attr[1];
        attr[0].id = cudaLaunchAttributeProgrammaticStreamSerialization;
        attr[0].val.programmaticStreamSerializationAllowed = 1;
        cfg.attrs = attr;
        cfg.numAttrs = 1;
        cudaLaunchKernelEx(&cfg, reduce_gelu_scatter_kernel, bias, out);
    }
}

// round 13
// speedup vs baseline: 1.1192x; 1.0428x over previous
#include <cuda_runtime.h>
#include <math.h>

// Problem constants
#define S        2048
#define ROWS     65536            // 2*16*2048 rows of x; also 32*2048 gemm outputs
#define TNB      64               // t-tile per partial-GEMM block
#define KCB      64               // k-chunk per partial-GEMM block
#define KSPLIT   32               // 2048 / KCB
#define NTILES   (S / TNB)        // 32 t-tiles
#define SMPAD    68               // smem row stride (words): 16B-aligned, 68%32=4 -> conflict-free

// Scratch (allocation-free rule: __device__ globals)
__device__ int   g_idx[ROWS];
__device__ float g_gather[ROWS];
__device__ float g_part[KSPLIT * ROWS];   // 8 MB fp32 partials [ks][m][t]

// ---------------------------------------------------------------------------
// Kernel A: one block per row. Copy x->out (float4) while reducing
// first-occurrence argmax of the row. 6.8-6.9 TB/s over 6 rounds — at the
// practical HBM ceiling; frozen.
// ---------------------------------------------------------------------------
__global__ void __launch_bounds__(256)
copy_argmax_kernel(const float* __restrict__ x, float* __restrict__ out)
{
    const int row = blockIdx.x;
    const float4* __restrict__ xr = (const float4*)(x + (size_t)row * S);
    float4* __restrict__ orow     = (float4*)(out + (size_t)row * S);

    const int t = threadIdx.x;

    float best = -INFINITY;
    int   bidx = 0;

    #pragma unroll
    for (int i = 0; i < 2; i++) {
        const int e = t + i * 256;          // float4 index in row (0..511)
        float4 v = xr[e];
        orow[e] = v;
        const int base = e * 4;
        if (v.x > best) { best = v.x; bidx = base + 0; }
        if (v.y > best) { best = v.y; bidx = base + 1; }
        if (v.z > best) { best = v.z; bidx = base + 2; }
        if (v.w > best) { best = v.w; bidx = base + 3; }
    }

    #pragma unroll
    for (int off = 16; off > 0; off >>= 1) {
        float ov = __shfl_down_sync(0xFFFFFFFFu, best, off);
        int   oi = __shfl_down_sync(0xFFFFFFFFu, bidx, off);
        if (ov > best || (ov == best && oi < bidx)) { best = ov; bidx = oi; }
    }

    __shared__ float sv[8];
    __shared__ int   si[8];
    const int lane = t & 31;
    const int warp = t >> 5;
    if (lane == 0) { sv[warp] = best; si[warp] = bidx; }
    __syncthreads();

    if (warp == 0) {
        best = (lane < 8) ? sv[lane] : -INFINITY;
        bidx = (lane < 8) ? si[lane] : 0x7FFFFFFF;
        #pragma unroll
        for (int off = 4; off > 0; off >>= 1) {
            float ov = __shfl_down_sync(0xFFFFFFFFu, best, off);
            int   oi = __shfl_down_sync(0xFFFFFFFFu, bidx, off);
            if (ov > best || (ov == best && oi < bidx)) { best = ov; bidx = oi; }
        }
        if (lane == 0) {
            g_idx[row]    = bidx;
            g_gather[row] = best;
        }
    }
}

// ---------------------------------------------------------------------------
// Async-copy + mma helpers
// ---------------------------------------------------------------------------
__device__ __forceinline__ void cp_async16(void* smem_dst, const void* gmem_src) {
    unsigned saddr = (unsigned)__cvta_generic_to_shared(smem_dst);
    asm volatile("cp.async.cg.shared.global [%0], [%1], 16;\n"
                 :: "r"(saddr), "l"(gmem_src));
}
__device__ __forceinline__ void cp_async_commit() {
    asm volatile("cp.async.commit_group;\n" ::: "memory");
}
__device__ __forceinline__ void cp_async_wait_all() {
    asm volatile("cp.async.wait_all;\n" ::: "memory");
}

__device__ __forceinline__ void mma_tf32_16x8x8(
    float& c0, float& c1, float& c2, float& c3,
    unsigned a0, unsigned a1, unsigned a2, unsigned a3,
    unsigned b0, unsigned b1)
{
    asm volatile(
        "mma.sync.aligned.m16n8k8.row.col.f32.tf32.tf32.f32 "
        "{%0,%1,%2,%3}, {%4,%5,%6,%7}, {%8,%9}, {%0,%1,%2,%3};"
        : "+f"(c0), "+f"(c1), "+f"(c2), "+f"(c3)
        : "r"(a0), "r"(a1), "r"(a2), "r"(a3), "r"(b0), "r"(b1));
}

// ---------------------------------------------------------------------------
// Kernel B1: k-split partial GEMM on tensor cores (tf32 mma.sync).
// Grid (32, 32) = 1024 blocks, 128 threads (4 warps).
// Fills via cp.async: W issued BEFORE cudaGridDependencySynchronize (in
// flight across the wait), gather after, one wait_all. Raw fp32 bits fed to
// tf32 mma (HW truncates low mantissa). Smem stride 68 -> conflict-free.
// ---------------------------------------------------------------------------
__global__ void __launch_bounds__(128)
gemm_partial_kernel(const float* __restrict__ W)
{
    __shared__ __align__(16) unsigned gs[32 * SMPAD];   // [m][k] fp32 bits
    __shared__ __align__(16) unsigned ws[TNB * SMPAD];  // [t][k] fp32 bits

    const int t0  = blockIdx.x * TNB;
    const int k0  = blockIdx.y * KCB;
    const int tid = threadIdx.x;

    // --- A-independent: W tile cp.async (overlaps the grid-dependency wait) ---
    {
        const int t  = tid >> 1;            // 0..63
        const int cb = (tid & 1) * 32;      // 0 or 32
        const float* src = W + (size_t)(t0 + t) * S + k0 + cb;
        unsigned*    dst = ws + t * SMPAD + cb;
        #pragma unroll
        for (int j = 0; j < 8; j++)
            cp_async16(dst + j * 4, src + j * 4);
    }
    cp_async_commit();

    cudaGridDependencySynchronize();

    // --- gather tile cp.async ---
    {
        const int m  = tid >> 2;            // 0..31
        const int cb = (tid & 3) * 16;      // 0,16,32,48
        const float* src = g_gather + (size_t)m * S + k0 + cb;
        unsigned*    dst = gs + m * SMPAD + cb;
        #pragma unroll
        for (int j = 0; j < 4; j++)
            cp_async16(dst + j * 4, src + j * 4);
    }
    cp_async_commit();
    cp_async_wait_all();
    __syncthreads();

    const int lane = tid & 31;
    const int w    = tid >> 5;
    const int mh   = (w & 1) * 16;     // m-half base
    const int tq   = (w >> 1) * 32;    // t-quarter base

    const int ar = lane >> 2;          // 0..7
    const int ac = lane & 3;           // 0..3

    float c[4][4] = {};

    #pragma unroll
    for (int ks = 0; ks < 8; ks++) {
        const int col = ks * 8 + ac;
        const unsigned a0 = gs[(mh + ar    ) * SMPAD + col];
        const unsigned a1 = gs[(mh + ar + 8) * SMPAD + col];
        const unsigned a2 = gs[(mh + ar    ) * SMPAD + col + 4];
        const unsigned a3 = gs[(mh + ar + 8) * SMPAD + col + 4];
        #pragma unroll
        for (int nt = 0; nt < 4; nt++) {
            const int n = tq + nt * 8 + ar;          // B[k][n] = ws[n][k]
            const unsigned b0 = ws[n * SMPAD + col];
            const unsigned b1 = ws[n * SMPAD + col + 4];
            mma_tf32_16x8x8(c[nt][0], c[nt][1], c[nt][2], c[nt][3],
                            a0, a1, a2, a3, b0, b1);
        }
    }

    // Store partials. C frag m16n8: (c0,c1) at row mh+ar, cols 2*ac, 2*ac+1;
    // (c2,c3) at row mh+ar+8.
    float* p = g_part + (size_t)blockIdx.y * ROWS;
    #pragma unroll
    for (int nt = 0; nt < 4; nt++) {
        const int tcol = t0 + tq + nt * 8 + 2 * ac;
        *(float2*)(p + (size_t)(mh + ar    ) * S + tcol) = make_float2(c[nt][0], c[nt][1]);
        *(float2*)(p + (size_t)(mh + ar + 8) * S + tcol) = make_float2(c[nt][2], c[nt][3]);
    }
}

// ---------------------------------------------------------------------------
// Kernel B2: reduce KSPLIT partials (fixed ks order -> deterministic), + bias,
// exact-erf GELU, scatter into out. 256 blocks x 128 threads, 2 outputs each
// via float2 over the L2-resident partials. PDL.
// ---------------------------------------------------------------------------
__global__ void __launch_bounds__(128)
reduce_gelu_scatter_kernel(const float* __restrict__ bias,
                           float* __restrict__ out)
{
    const int r2 = (blockIdx.x * 128 + threadIdx.x) * 2;   // base of 2 outputs
    const int t  = r2 & (S - 1);
    const float bv0 = bias[t];
    const float bv1 = bias[t + 1];       // r2 even, t+1 < S (S even)

    cudaGridDependencySynchronize();

    float2 s = make_float2(0.f, 0.f);
    #pragma unroll
    for (int ks = 0; ks < KSPLIT; ks++) {
        float2 v = *(const float2*)(g_part + (size_t)ks * ROWS + r2);
        s.x += v.x; s.y += v.y;
    }

    const float v0  = s.x + bv0;
    const float v1  = s.y + bv1;
    const float g0 = 0.5f * v0 * (1.0f + erff(v0 * 0.70710678118654752f));
    const float g1 = 0.5f * v1 * (1.0f + erff(v1 * 0.70710678118654752f));
    out[(size_t)(r2    ) * S + (size_t)g_idx[r2    ]] = g0;
    out[(size_t)(r2 + 1) * S + (size_t)g_idx[r2 + 1]] = g1;
}

// ---------------------------------------------------------------------------
extern "C" void kernel_launch(void* const* d_in, const int* in_sizes, int n_in,
                              void* d_out, int out_size)
{
    const float* x    = (const float*)d_in[0];   // [2,16,2048,2048]
    const float* W    = (const float*)d_in[1];   // [2048,2048]
    const float* bias = (const float*)d_in[2];   // [2048]
    float* out        = (float*)d_out;

    copy_argmax_kernel<<<ROWS, 256>>>(x, out);

    {
        cudaLaunchConfig_t cfg = {};
        cfg.gridDim  = dim3(NTILES, KSPLIT);
        cfg.blockDim = dim3(128);
        cfg.stream   = 0;
        cudaLaunchAttribute attr[1];
        attr[0].id = cudaLaunchAttributeProgrammaticStreamSerialization;
        attr[0].val.programmaticStreamSerializationAllowed = 1;
        cfg.attrs = attr;
        cfg.numAttrs = 1;
        cudaLaunchKernelEx(&cfg, gemm_partial_kernel, W);
    }

    {
        cudaLaunchConfig_t cfg = {};
        cfg.gridDim  = dim3(ROWS / 256);
        cfg.blockDim = dim3(128);
        cfg.stream   = 0;
        cudaLaunchAttribute attr[1];
        attr[0].id = cudaLaunchAttributeProgrammaticStreamSerialization;
        attr[0].val.programmaticStreamSerializationAllowed = 1;
        cfg.attrs = attr;
        cfg.numAttrs = 1;
        cudaLaunchKernelEx(&cfg, reduce_gelu_scatter_kernel, bias, out);
    }
}